// round 17
// baseline (speedup 1.0000x reference)
#include <cuda_runtime.h>
#include <cuda_fp16.h>
#include <mma.h>
#include <math.h>

using namespace nvcuda;

// Problem constants
#define Bb 4
#define Nn 16
#define Gg 64            // Bb*Nn
#define Ll 2048
#define Ee 32768
#define C0 64
#define Cc 128
#define C2 256
#define EPSf 1e-5

typedef unsigned long long ull;

// packed f32x2 FMA: d = a*b + d (elementwise on 2 packed floats)
#define FFMA2(d, a, b) asm("fma.rn.f32x2 %0, %1, %2, %3;" : "=l"(d) : "l"(a), "l"(b), "l"(d))

__device__ __forceinline__ ull dupu(unsigned x) {
    ull r; asm("mov.b64 %0, {%1, %1};" : "=l"(r) : "r"(x)); return r;
}
__device__ __forceinline__ ull dupf(float x) {
    ull r; asm("mov.b64 %0, {%1, %1};" : "=l"(r) : "f"(x)); return r;
}

// ---------------- scratch (static device globals; no allocation) ----------------
__device__ __half g_h0h [Gg*Ll*C0];   // transposed x        [g,l,64] fp16
__device__ float  g_agg0[Gg*Ll*C0];   // A @ h0              [g,l,64]
__device__ __half g_hWh [Gg*Ll*Cc];   // GEMM out pre-agg    [g,l,128] fp16
__device__ float  g_a   [Gg*Ll*Cc];   // post-agg (+bias)    [g,l,128]
__device__ float  g_U   [Bb*Ll*Cc];   // act(amax) @ W_up    [b,l,128]
__device__ float  g_amax[Bb*Ll*Cc];   // max over n of a     [b,l,128]

// Split-precision weights, row-major [K, 128]: W = hi + lo (both fp16)
__device__ __half g_W1h [C0*Cc],  g_W1l [C0*Cc];
__device__ __half g_W2Lh[Cc*Cc],  g_W2Ll[Cc*Cc];
__device__ __half g_W2Uh[Cc*Cc],  g_W2Ul[Cc*Cc];
__device__ __half g_W3Lh[Cc*Cc],  g_W3Ll[Cc*Cc];
__device__ __half g_W3Uh[Cc*Cc],  g_W3Ul[Cc*Cc];

__device__ double g_sum[C2], g_sumsq[C2];
__device__ float  g_scale[C2], g_shift[C2];

__device__ int   g_rowptr[Ll+1];
__device__ uint2 g_edge[Ee];         // {src_col, enorm_bits}
__device__ float g_selfnorm[Ll];

// ---------------- fused graph build: detect dtype + count + scan + fill ----------------
__global__ __launch_bounds__(1024) void graph_build(const unsigned int* __restrict__ w) {
    __shared__ int   s_any;
    __shared__ int   s_cnt[Ll];
    __shared__ int   s_base[Ll];
    __shared__ float s_dinv[Ll];
    __shared__ int   s_wsum[32];
    int tid = threadIdx.x;

    if (tid == 0) s_any = 0;
    s_cnt[tid] = 0; s_cnt[tid + 1024] = 0;
    __syncthreads();

    int any = 0;
    for (int i = 2 * tid + 1; i < 16384; i += 2048)
        if (w[i] != 0u) any = 1;
    if (any) s_any = 1;
    __syncthreads();
    const int is64 = (s_any == 0);

    for (int e = tid; e < Ee; e += 1024) {
        int d = (is64 ? (int)w[2 * (Ee + e)] : (int)w[Ee + e]) & (Ll - 1);
        atomicAdd(&s_cnt[d], 1);
    }
    __syncthreads();

    int n0 = 2 * tid, n1 = 2 * tid + 1;
    int v0 = s_cnt[n0], v1 = s_cnt[n1];
    int s = v0 + v1;
    int lane = tid & 31, wid = tid >> 5;
    int own = s;
    #pragma unroll
    for (int off = 1; off < 32; off <<= 1) {
        int t = __shfl_up_sync(0xffffffffu, s, off);
        if (lane >= off) s += t;
    }
    if (lane == 31) s_wsum[wid] = s;
    __syncthreads();
    if (wid == 0) {
        int t = s_wsum[lane];
        int o = t;
        #pragma unroll
        for (int off = 1; off < 32; off <<= 1) {
            int u = __shfl_up_sync(0xffffffffu, t, off);
            if (lane >= off) t += u;
        }
        s_wsum[lane] = t - o;
    }
    __syncthreads();
    int run = s_wsum[wid] + s - own;

    g_rowptr[n0] = run;  s_base[n0] = run;
    float deg0 = (float)v0 + 2.0f;
    s_dinv[n0] = rsqrtf(deg0); g_selfnorm[n0] = 2.0f / deg0;
    int run1 = run + v0;
    g_rowptr[n1] = run1; s_base[n1] = run1;
    float deg1 = (float)v1 + 2.0f;
    s_dinv[n1] = rsqrtf(deg1); g_selfnorm[n1] = 2.0f / deg1;
    if (tid == 1023) g_rowptr[Ll] = run1 + v1;
    s_cnt[n0] = 0; s_cnt[n1] = 0;
    __syncthreads();

    for (int e = tid; e < Ee; e += 1024) {
        int sN = (is64 ? (int)w[2 * e]        : (int)w[e])        & (Ll - 1);
        int d  = (is64 ? (int)w[2 * (Ee + e)] : (int)w[Ee + e])   & (Ll - 1);
        int pos = s_base[d] + atomicAdd(&s_cnt[d], 1);
        g_edge[pos] = make_uint2((unsigned)sN, __float_as_uint(s_dinv[sN] * s_dinv[d]));
    }
}

// ---------------- fused setup: split-pack weights + transpose x ----------------
__device__ __forceinline__ void pack_w(__half* hi, __half* lo, int idx, float v) {
    __half h = __float2half_rn(v);
    hi[idx] = h;
    lo[idx] = __float2half_rn(v - __half2float(h));
}

__global__ __launch_bounds__(256) void setup_kernel(const float* __restrict__ x,
                                                    const float* __restrict__ W1,
                                                    const float* __restrict__ W2,
                                                    const float* __restrict__ W3) {
    __shared__ float t[32][33];
    int bid = blockIdx.x;
    if (bid < 288) {
        int flat = bid * 256 + threadIdx.x;      // 0 .. 73727
        if (flat < C0 * Cc) {                    // W1
            pack_w(g_W1h, g_W1l, flat, W1[flat]);
        } else {
            int f = flat - C0 * Cc;
            int tsel = f >> 14;                  // 0..3 : W2L, W2U, W3L, W3U
            int r = f & 16383;                   // k*128+n within the half
            int k = r >> 7, n = r & 127;
            const float* W = (tsel < 2) ? W2 : W3;
            int krow = (tsel & 1) ? (k + Cc) : k;
            __half* hi = (tsel == 0) ? g_W2Lh : (tsel == 1) ? g_W2Uh : (tsel == 2) ? g_W3Lh : g_W3Uh;
            __half* lo = (tsel == 0) ? g_W2Ll : (tsel == 1) ? g_W2Ul : (tsel == 2) ? g_W3Ll : g_W3Ul;
            pack_w(hi, lo, r, W[krow * Cc + n]);
        }
        return;
    }
    int b = bid - 288;                // 0 .. 8191
    int lblk = b & 63;
    int cblk = (b >> 6) & 1;
    int g    = b >> 7;
    int tx = threadIdx.x & 31, ty = threadIdx.x >> 5;
    int c0 = cblk * 32, l0 = lblk * 32;
    #pragma unroll
    for (int i = 0; i < 32; i += 8) {
        int c = c0 + ty + i, l = l0 + tx;
        t[ty + i][tx] = x[((size_t)(g * C0 + c)) * Ll + l];
    }
    __syncthreads();
    #pragma unroll
    for (int i = 0; i < 32; i += 8) {
        int l = l0 + ty + i, c = c0 + tx;
        g_h0h[((size_t)g * Ll + l) * C0 + c] = __float2half(t[tx][ty + i]);
    }
}

// ---------------- aggregation layer 1 (fp16 uint4 payload, 64ch, 8 lanes/node) ----------------
__global__ __launch_bounds__(128) void agg1_kernel() {
    int lane = threadIdx.x & 7;
    int nidx = threadIdx.x >> 3;                      // 16 nodes/block
    size_t ng = (size_t)blockIdx.x * 16 + nidx;
    int node = (int)(ng & (Ll - 1));
    size_t g = ng / Ll;
    const uint4* Xg = (const uint4*)(g_h0h + g * (size_t)Ll * C0);

    ull acc[4] = {0ull, 0ull, 0ull, 0ull};
    {
        ull sn2 = dupf(g_selfnorm[node]);
        uint4 hv = Xg[(size_t)node * 8 + lane];
        float2 f0 = __half22float2(*(const __half2*)&hv.x); FFMA2(acc[0], *(ull*)&f0, sn2);
        float2 f1 = __half22float2(*(const __half2*)&hv.y); FFMA2(acc[1], *(ull*)&f1, sn2);
        float2 f2 = __half22float2(*(const __half2*)&hv.z); FFMA2(acc[2], *(ull*)&f2, sn2);
        float2 f3 = __half22float2(*(const __half2*)&hv.w); FFMA2(acc[3], *(ull*)&f3, sn2);
    }
    int s = g_rowptr[node], e = g_rowptr[node + 1];
    for (int i = s; i < e; i++) {
        uint2 ed = g_edge[i];
        ull nw2 = dupu(ed.y);
        uint4 v = Xg[(size_t)ed.x * 8 + lane];
        float2 a0 = __half22float2(*(const __half2*)&v.x); FFMA2(acc[0], *(ull*)&a0, nw2);
        float2 a1 = __half22float2(*(const __half2*)&v.y); FFMA2(acc[1], *(ull*)&a1, nw2);
        float2 a2 = __half22float2(*(const __half2*)&v.z); FFMA2(acc[2], *(ull*)&a2, nw2);
        float2 a3 = __half22float2(*(const __half2*)&v.w); FFMA2(acc[3], *(ull*)&a3, nw2);
    }
    float2 p0 = *(float2*)&acc[0], p1 = *(float2*)&acc[1];
    float2 p2 = *(float2*)&acc[2], p3 = *(float2*)&acc[3];
    ((float4*)g_agg0)[ng * 16 + lane * 2]     = make_float4(p0.x, p0.y, p1.x, p1.y);
    ((float4*)g_agg0)[ng * 16 + lane * 2 + 1] = make_float4(p2.x, p2.y, p3.x, p3.y);
}

// ---------------- aggregation layers 2/3 (fp16 uint4 payload, 128ch, 16 lanes/node) ----------------
__global__ __launch_bounds__(128) void agg2_kernel(const float* __restrict__ bias) {
    if (blockIdx.x == 0) {
        int t = threadIdx.x;
        g_sum[t] = 0.0;       g_sumsq[t] = 0.0;
        g_sum[Cc + t] = 0.0;  g_sumsq[Cc + t] = 0.0;
    }
    int lane = threadIdx.x & 15;
    int nidx = threadIdx.x >> 4;                      // 8 nodes/block
    size_t ng = (size_t)blockIdx.x * 8 + nidx;
    int node = (int)(ng & (Ll - 1));
    size_t g = ng / Ll;
    const uint4* Xg = (const uint4*)(g_hWh + g * (size_t)Ll * Cc);

    ull acc[4] = {0ull, 0ull, 0ull, 0ull};
    {
        ull sn2 = dupf(g_selfnorm[node]);
        uint4 hv = Xg[(size_t)node * 16 + lane];
        float2 f0 = __half22float2(*(const __half2*)&hv.x); FFMA2(acc[0], *(ull*)&f0, sn2);
        float2 f1 = __half22float2(*(const __half2*)&hv.y); FFMA2(acc[1], *(ull*)&f1, sn2);
        float2 f2 = __half22float2(*(const __half2*)&hv.z); FFMA2(acc[2], *(ull*)&f2, sn2);
        float2 f3 = __half22float2(*(const __half2*)&hv.w); FFMA2(acc[3], *(ull*)&f3, sn2);
    }
    int s = g_rowptr[node], e = g_rowptr[node + 1];
    for (int i = s; i < e; i++) {
        uint2 ed = g_edge[i];
        ull nw2 = dupu(ed.y);
        uint4 v = Xg[(size_t)ed.x * 16 + lane];
        float2 a0 = __half22float2(*(const __half2*)&v.x); FFMA2(acc[0], *(ull*)&a0, nw2);
        float2 a1 = __half22float2(*(const __half2*)&v.y); FFMA2(acc[1], *(ull*)&a1, nw2);
        float2 a2 = __half22float2(*(const __half2*)&v.z); FFMA2(acc[2], *(ull*)&a2, nw2);
        float2 a3 = __half22float2(*(const __half2*)&v.w); FFMA2(acc[3], *(ull*)&a3, nw2);
    }
    float2 p0 = *(float2*)&acc[0], p1 = *(float2*)&acc[1];
    float2 p2 = *(float2*)&acc[2], p3 = *(float2*)&acc[3];
    float4 b0 = ((const float4*)bias)[lane * 2];
    float4 b1 = ((const float4*)bias)[lane * 2 + 1];
    ((float4*)g_a)[ng * 32 + lane * 2]     = make_float4(p0.x + b0.x, p0.y + b0.y, p1.x + b0.z, p1.y + b0.w);
    ((float4*)g_a)[ng * 32 + lane * 2 + 1] = make_float4(p2.x + b1.x, p2.y + b1.y, p3.x + b1.z, p3.y + b1.w);
}

// ---------------- wmma GEMM: Y[64 rows, 128] = act(X[*,K]) @ (Whi+Wlo)[K,128] (+U)(+bias) ----------------
// 256 threads = 8 warps (4m x 2n). A split hi/lo fp16 in smem; W hi/lo fragment-loaded from global.
// 3 mma per tile (hi*hi + lo*hi + hi*lo) => fp32-accurate product.
template <int K, bool ADD_U, bool ADD_BIAS, bool ACT, bool HALF_OUT>
__device__ __forceinline__ void wmma_gemm_body(
    const float* __restrict__ X,
    const __half* __restrict__ Whi, const __half* __restrict__ Wlo,
    const float* __restrict__ bias, const float* __restrict__ U,
    const float* __restrict__ scale, const float* __restrict__ shift,
    float* __restrict__ Yf, __half* __restrict__ Yh)
{
    __shared__ __align__(16) char sraw[32768];         // A hi/lo (<=32KB) aliased with epilogue fp32 (32KB)
    __shared__ float s_sc[Cc], s_sh[Cc], s_b[Cc];
    __half* sAhi = (__half*)sraw;
    __half* sAlo = sAhi + 64 * K;
    float*  sOut = (float*)sraw;

    int tid = threadIdx.x;
    int wid = tid >> 5;
    int wm = wid & 3, wn = wid >> 2;                   // warp row/col
    size_t row0 = (size_t)blockIdx.x * 64;

    if (ACT && tid < K) { s_sc[tid] = scale[tid]; s_sh[tid] = shift[tid]; }
    if (ADD_BIAS && tid < Cc) s_b[tid] = bias[tid];
    __syncthreads();

    // stage A (64 rows x K) with optional act, split into hi/lo fp16
    {
        const float4* Xv = (const float4*)(X + row0 * K);
        #pragma unroll
        for (int i = tid; i < 64 * K / 4; i += 256) {
            float4 v = Xv[i];
            int cc = (i * 4) % K;
            if (ACT) {
                v.x = fmaxf(0.f, fmaf(v.x, s_sc[cc + 0], s_sh[cc + 0]));
                v.y = fmaxf(0.f, fmaf(v.y, s_sc[cc + 1], s_sh[cc + 1]));
                v.z = fmaxf(0.f, fmaf(v.z, s_sc[cc + 2], s_sh[cc + 2]));
                v.w = fmaxf(0.f, fmaf(v.w, s_sc[cc + 3], s_sh[cc + 3]));
            }
            __half h0 = __float2half_rn(v.x), h1 = __float2half_rn(v.y);
            __half h2 = __float2half_rn(v.z), h3 = __float2half_rn(v.w);
            __half2* dh = (__half2*)(sAhi + i * 4);
            dh[0] = __halves2half2(h0, h1);
            dh[1] = __halves2half2(h2, h3);
            __half2* dl = (__half2*)(sAlo + i * 4);
            dl[0] = __halves2half2(__float2half_rn(v.x - __half2float(h0)),
                                   __float2half_rn(v.y - __half2float(h1)));
            dl[1] = __halves2half2(__float2half_rn(v.z - __half2float(h2)),
                                   __float2half_rn(v.w - __half2float(h3)));
        }
    }
    __syncthreads();

    wmma::fragment<wmma::accumulator, 16, 16, 16, float> acc[4];
    #pragma unroll
    for (int j = 0; j < 4; j++) wmma::fill_fragment(acc[j], 0.0f);

    #pragma unroll
    for (int k0 = 0; k0 < K; k0 += 16) {
        wmma::fragment<wmma::matrix_a, 16, 16, 16, __half, wmma::row_major> ah, al;
        wmma::load_matrix_sync(ah, sAhi + (wm * 16) * K + k0, K);
        wmma::load_matrix_sync(al, sAlo + (wm * 16) * K + k0, K);
        #pragma unroll
        for (int j = 0; j < 4; j++) {
            int n0 = wn * 64 + j * 16;
            wmma::fragment<wmma::matrix_b, 16, 16, 16, __half, wmma::row_major> bh, bl;
            wmma::load_matrix_sync(bh, Whi + k0 * Cc + n0, Cc);
            wmma::load_matrix_sync(bl, Wlo + k0 * Cc + n0, Cc);
            wmma::mma_sync(acc[j], ah, bh, acc[j]);
            wmma::mma_sync(acc[j], al, bh, acc[j]);
            wmma::mma_sync(acc[j], ah, bl, acc[j]);
        }
    }

    __syncthreads();   // done reading A from smem; reuse as epilogue buffer
    #pragma unroll
    for (int j = 0; j < 4; j++)
        wmma::store_matrix_sync(sOut + (wm * 16) * Cc + wn * 64 + j * 16, acc[j], Cc, wmma::mem_row_major);
    __syncthreads();

    // write-out: 4 threads per row, 32 cols each
    int r = tid >> 2;
    int cbase = (tid & 3) * 32;
    size_t row = row0 + r;
    size_t l = row % Ll;
    size_t b = row / ((size_t)Nn * Ll);
    const float* Up = ADD_U ? (U + (b * Ll + l) * Cc) : nullptr;
    const float* src = sOut + r * Cc + cbase;
    if (HALF_OUT) {
        unsigned o[16];
        #pragma unroll
        for (int i = 0; i < 16; i++) {
            float v0 = src[2 * i], v1 = src[2 * i + 1];
            if (ADD_U) { v0 += Up[cbase + 2 * i]; v1 += Up[cbase + 2 * i + 1]; }
            __half2 hh = __floats2half2_rn(v0, v1);
            o[i] = *(unsigned*)&hh;
        }
        uint4* dstv = (uint4*)(Yh + row * Cc + cbase);
        #pragma unroll
        for (int j = 0; j < 4; j++) dstv[j] = ((uint4*)o)[j];
    } else {
        float o[32];
        #pragma unroll
        for (int i = 0; i < 32; i++) {
            float v = src[i];
            if (ADD_U)    v += Up[cbase + i];
            if (ADD_BIAS) v += s_b[cbase + i];
            o[i] = v;
        }
        float4* dstv = (float4*)(Yf + row * Cc + cbase);
        #pragma unroll
        for (int j = 0; j < 8; j++) dstv[j] = ((float4*)o)[j];
    }
}

__global__ __launch_bounds__(256) void gemm1_kernel(const float* __restrict__ bias) {
    if (blockIdx.x == 0 && threadIdx.x < 128) {   // zero BN stat accumulators
        g_sum[threadIdx.x] = 0.0;       g_sumsq[threadIdx.x] = 0.0;
        g_sum[Cc + threadIdx.x] = 0.0;  g_sumsq[Cc + threadIdx.x] = 0.0;
    }
    wmma_gemm_body<C0, false, true, false, false>(g_agg0, g_W1h, g_W1l, bias, nullptr,
                                                  nullptr, nullptr, g_a, nullptr);
}
// U = relu(bn(amax)) @ W_up      (upper-half BN params: offset Cc)
__global__ __launch_bounds__(256) void gemmU_kernel(int wsel) {
    const __half* hi = (wsel == 2) ? g_W2Uh : g_W3Uh;
    const __half* lo = (wsel == 2) ? g_W2Ul : g_W3Ul;
    wmma_gemm_body<Cc, false, false, true, false>(g_amax, hi, lo, nullptr, nullptr,
                                                  g_scale + Cc, g_shift + Cc, g_U, nullptr);
}
// hW = relu(bn(a)) @ W_low + U[b]  -> fp16 output for the gather
__global__ __launch_bounds__(256) void gemmM_kernel(int wsel) {
    const __half* hi = (wsel == 2) ? g_W2Lh : g_W3Lh;
    const __half* lo = (wsel == 2) ? g_W2Ll : g_W3Ll;
    wmma_gemm_body<Cc, true, false, true, true>(g_a, hi, lo, nullptr, g_U,
                                                g_scale, g_shift, nullptr, g_hWh);
}

// ---------------- fused amax + BN stats: ONE pass over g_a ----------------
__global__ void amax_stats_kernel() {
    int c = threadIdx.x;
    float s_a = 0.f, ss_a = 0.f, s_m = 0.f, ss_m = 0.f;
    size_t base = (size_t)blockIdx.x * 8;
    #pragma unroll 1
    for (int j = 0; j < 8; j++) {
        size_t bl = base + j;
        size_t b = bl / Ll, l = bl % Ll;
        const float* p = g_a + ((b * Nn) * Ll + l) * Cc + c;
        float m = -3.4e38f;
        #pragma unroll
        for (int n = 0; n < Nn; n++) {
            float v = p[(size_t)n * Ll * Cc];
            s_a += v; ss_a += v * v;
            m = fmaxf(m, v);
        }
        g_amax[bl * Cc + c] = m;
        s_m += m; ss_m += m * m;
    }
    atomicAdd(&g_sum[c],        (double)s_a);
    atomicAdd(&g_sumsq[c],      (double)ss_a);
    atomicAdd(&g_sum[Cc + c],   (double)s_m);
    atomicAdd(&g_sumsq[Cc + c], (double)ss_m);
}

__global__ void bn_kernel(const float* __restrict__ gamma, const float* __restrict__ beta) {
    int c = threadIdx.x;
    double cnt = (c < Cc) ? (double)((size_t)Gg * Ll) : (double)((size_t)Bb * Ll);
    double mean = g_sum[c] / cnt;
    double var  = g_sumsq[c] / cnt - mean * mean;
    double inv  = 1.0 / sqrt(var + (double)EPSf);
    double sc   = (double)gamma[c] * inv;
    g_scale[c] = (float)sc;
    g_shift[c] = (float)((double)beta[c] - mean * sc);
}

// ---------------- final: BN+relu+concat+transpose to out [g, 256, l] ----------------
__global__ void final_kernel(float* __restrict__ out) {
    __shared__ float t[32][33];
    int g = blockIdx.z, c0 = blockIdx.y * 32, l0 = blockIdx.x * 32;
    int tx = threadIdx.x, ty = threadIdx.y;
    #pragma unroll
    for (int i = 0; i < 32; i += 8) {
        int l = l0 + ty + i;
        int c = c0 + tx;
        float v;
        if (c < Cc) v = g_a[((size_t)g * Ll + l) * Cc + c];
        else        v = g_amax[((size_t)(g / Nn) * Ll + l) * Cc + (c - Cc)];
        v = fmaxf(0.f, fmaf(v, g_scale[c], g_shift[c]));
        t[ty + i][tx] = v;
    }
    __syncthreads();
    #pragma unroll
    for (int i = 0; i < 32; i += 8) {
        int c = c0 + ty + i;
        int l = l0 + tx;
        out[((size_t)g * C2 + c) * Ll + l] = t[tx][ty + i];
    }
}

// ---------------- launch ----------------
extern "C" void kernel_launch(void* const* d_in, const int* in_sizes, int n_in,
                              void* d_out, int out_size) {
    const float* x  = (const float*)d_in[0];
    const void*  ei = d_in[1];
    const float *W1 = (const float*)d_in[2],  *b1  = (const float*)d_in[3];
    const float *W2 = (const float*)d_in[4],  *b2  = (const float*)d_in[5];
    const float *W3 = (const float*)d_in[6],  *b3  = (const float*)d_in[7];
    const float *ga1 = (const float*)d_in[8],  *be1 = (const float*)d_in[9];
    const float *ga2 = (const float*)d_in[10], *be2 = (const float*)d_in[11];
    const float *ga3 = (const float*)d_in[12], *be3 = (const float*)d_in[13];
    float* out = (float*)d_out;

    const int rowsGL = Gg * Ll;   // 131072
    const int rowsBL = Bb * Ll;   // 8192

    setup_kernel<<<288 + 8192, 256>>>(x, W1, W2, W3);
    graph_build<<<1, 1024>>>((const unsigned int*)ei);

    // ---- layer 1 ----
    agg1_kernel<<<rowsGL / 16, 128>>>();          // idx 2
    gemm1_kernel<<<rowsGL / 64, 256>>>(b1);       // idx 3 -> ncu capture (wmma); zeroes BN accums
    amax_stats_kernel<<<rowsBL / 8, 128>>>();
    bn_kernel<<<1, C2>>>(ga1, be1);

    // ---- layer 2 ----
    gemmU_kernel<<<rowsBL / 64, 256>>>(2);
    gemmM_kernel<<<rowsGL / 64, 256>>>(2);
    agg2_kernel<<<rowsGL / 8, 128>>>(b2);
    amax_stats_kernel<<<rowsBL / 8, 128>>>();
    bn_kernel<<<1, C2>>>(ga2, be2);

    // ---- layer 3 ----
    gemmU_kernel<<<rowsBL / 64, 256>>>(3);
    gemmM_kernel<<<rowsGL / 64, 256>>>(3);
    agg2_kernel<<<rowsGL / 8, 128>>>(b3);
    amax_stats_kernel<<<rowsBL / 8, 128>>>();
    bn_kernel<<<1, C2>>>(ga3, be3);

    final_kernel<<<dim3(Ll / 32, C2 / 32, Gg), dim3(32, 8)>>>(out);
}